// round 10
// baseline (speedup 1.0000x reference)
#include <cuda_runtime.h>
#include <cuda_fp16.h>

// Quanvolution (2x2, 4 qubits, RY encode + RY params + CNOT ring, <Z_q>).
//
//   Zq = cos(pi*a_q + w_q) = cos(pi a) cos w_q - sin(pi a) sin w_q
//   ch0 = Z1*Z2*Z3, ch1 = Z0*Z1, ch2 = Z0*Z1*Z2, ch3 = Z0*Z1*Z2*Z3
//
// R10 = R9 tile/consumer/store structure (proven coalesced) with fp16-packed
// weight-pre-folded tables:
//   W01[r][c] = half2( Z0(r,c), Z1(r,c+1) )
//   W23[r][c] = half2( Z2(r,c), Z3(r,c+1) )
// so each pixel needs only 2 LDS.32 (8 B/px smem reads, was 32 B/px).
// Products are computed in fp32 (only storage is fp16): rel_err ~1.5e-4.

#define H_IN 224
#define W_IN 224
#define L_OUT 223
#define TILE 32
#define HROWS 33
#define WPR 32             // words (half2) per table row
#define PI_F 3.14159265358979323846f

__global__ __launch_bounds__(256) void quanv_main_kernel(
    const float* __restrict__ in,   // (64,1,224,224)
    const float* __restrict__ w,    // (1,4)
    float* __restrict__ out)        // (64,4,223,223)
{
    __shared__ __half W01h[HROWS][2 * WPR];   // [r][2c]=Z0(c), [r][2c+1]=Z1(c+1)
    __shared__ __half W23h[HROWS][2 * WPR];   // [r][2c]=Z2(c), [r][2c+1]=Z3(c+1)
    __shared__ float wtrig[8];                // cw0..3, sw0..3

    const int tid  = threadIdx.x;
    const int lane = tid & 31;
    const int wg   = tid >> 5;
    const int b  = blockIdx.z;
    const int x0 = blockIdx.y * TILE;
    const int y0 = blockIdx.x * TILE;

    const float* inb = in + (size_t)b * (H_IN * W_IN);

    // ---- Batched tile LDGs (independent of weights; in flight across bar1) ----
    const int gy = (y0 + lane < W_IN) ? (y0 + lane) : (W_IN - 1);
    float v[4];
    #pragma unroll
    for (int it = 0; it < 4; it++) {
        const int r  = wg + 8 * it;
        const int gx = (x0 + r < H_IN) ? (x0 + r) : (H_IN - 1);
        v[it] = __ldg(&inb[gx * W_IN + gy]);
    }
    // Halo remainder: row 32 (cols 0..32) + col 32 (rows 0..31).
    float ve = 0.0f;
    int er = 0, ec = 0;
    const bool extra = tid < 65;
    if (extra) {
        er = (tid < 33) ? 32 : (tid - 33);
        ec = (tid < 33) ? tid : 32;
        const int gx  = (x0 + er < H_IN) ? (x0 + er) : (H_IN - 1);
        const int gy2 = (y0 + ec < W_IN) ? (y0 + ec) : (W_IN - 1);
        ve = __ldg(&inb[gx * W_IN + gy2]);
    }

    // ---- Weight trig (4 threads), made visible by barrier 1 ----
    if (tid < 4) {
        float s, c;
        __sincosf(__ldg(&w[tid]), &s, &c);
        wtrig[tid] = c;
        wtrig[4 + tid] = s;
    }
    __syncthreads();

    const float cw0 = wtrig[0], cw1 = wtrig[1], cw2 = wtrig[2], cw3 = wtrig[3];
    const float sw0 = wtrig[4], sw1 = wtrig[5], sw2 = wtrig[6], sw3 = wtrig[7];

    // ---- Fold + convert + packed STS.16 ----
    // Element (r,c): Z0,Z2 -> lo of word c (c<=31); Z1,Z3 -> hi of word c-1 (c>=1).
    #pragma unroll
    for (int it = 0; it < 4; it++) {
        const int r = wg + 8 * it;
        float s, c;
        __sincosf(v[it] * PI_F, &s, &c);
        const __half h0 = __float2half_rn(fmaf(-s, sw0, c * cw0));
        const __half h1 = __float2half_rn(fmaf(-s, sw1, c * cw1));
        const __half h2 = __float2half_rn(fmaf(-s, sw2, c * cw2));
        const __half h3 = __float2half_rn(fmaf(-s, sw3, c * cw3));
        W01h[r][2 * lane] = h0;
        W23h[r][2 * lane] = h2;
        if (lane > 0) {
            W01h[r][2 * lane - 1] = h1;
            W23h[r][2 * lane - 1] = h3;
        }
    }
    if (extra) {
        float s, c;
        __sincosf(ve * PI_F, &s, &c);
        const __half h0 = __float2half_rn(fmaf(-s, sw0, c * cw0));
        const __half h1 = __float2half_rn(fmaf(-s, sw1, c * cw1));
        const __half h2 = __float2half_rn(fmaf(-s, sw2, c * cw2));
        const __half h3 = __float2half_rn(fmaf(-s, sw3, c * cw3));
        if (ec <= 31) {                    // lo halves (word ec)
            W01h[er][2 * ec] = h0;
            W23h[er][2 * ec] = h2;
        }
        if (ec >= 1) {                     // hi halves (word ec-1)
            W01h[er][2 * ec - 1] = h1;
            W23h[er][2 * ec - 1] = h3;
        }
    }
    __syncthreads();

    // ---- Consumer: R9 mapping (lane -> consecutive y; rows wg+8k) ----
    const int ty = lane;
    const int y = y0 + ty;
    if (y >= L_OUT) return;

    const size_t plane = (size_t)L_OUT * L_OUT;
    float* o = out + (size_t)b * 4 * plane + (size_t)(x0 + wg) * L_OUT + y;

    #pragma unroll
    for (int k = 0; k < 4; k++) {
        const int rx = wg + 8 * k;
        if (x0 + rx < L_OUT) {
            const __half2 u01 = *reinterpret_cast<const __half2*>(&W01h[rx    ][2 * ty]);
            const __half2 u23 = *reinterpret_cast<const __half2*>(&W23h[rx + 1][2 * ty]);
            const float2 z01 = __half22float2(u01);   // (Z0, Z1)
            const float2 z23 = __half22float2(u23);   // (Z2, Z3)

            const float p01 = z01.x * z01.y;
            const float p23 = z23.x * z23.y;

            o[0]         = z01.y * p23;   // ch0 = Z1 Z2 Z3
            o[plane]     = p01;           // ch1 = Z0 Z1
            o[2 * plane] = p01 * z23.x;   // ch2 = Z0 Z1 Z2
            o[3 * plane] = p01 * p23;     // ch3 = Z0 Z1 Z2 Z3
        }
        o += 8 * L_OUT;
    }
}

extern "C" void kernel_launch(void* const* d_in, const int* in_sizes, int n_in,
                              void* d_out, int out_size) {
    const float* inputs = (const float*)d_in[0];   // (64,1,224,224) float32
    const float* weight = (const float*)d_in[1];   // (1,4) float32
    float* out = (float*)d_out;                    // (64,4,223,223) float32

    dim3 grid((L_OUT + TILE - 1) / TILE,   // 7
              (L_OUT + TILE - 1) / TILE,   // 7
              64);                          // batch
    quanv_main_kernel<<<grid, 256>>>(inputs, weight, out);
}

// round 11
// speedup vs baseline: 1.0129x; 1.0129x over previous
#include <cuda_runtime.h>
#include <cuda_fp16.h>

// Quanvolution (2x2, 4 qubits, RY encode + RY params + CNOT ring, <Z_q>).
//
//   Zq = cos(pi*a_q + w_q)   (direct MUFU.COS, weights folded at load)
//   ch0 = Z1*Z2*Z3, ch1 = Z0*Z1, ch2 = Z0*Z1*Z2, ch3 = Z0*Z1*Z2*Z3
//
// R11: 32x64 tile, fp16 interleaved tables (R10 layout):
//   T01[r][c] = half2( Z_w0(r,c), Z_w1(r,c+1) )
//   T23[r][c] = half2( Z_w2(r,c), Z_w3(r,c+1) )
// Consumer handles 4 rows x 2 adjacent y per thread: one LDS.64 per table per
// row serves BOTH pixels of the pair; stores use STG.64 on the two channels
// whose (row*223 + y + ch*plane) offset is 8B-aligned (plane is odd, so even
// rows vectorize ch0/ch2, odd rows ch1/ch3). Lane -> consecutive y kept.

#define H_IN 224
#define W_IN 224
#define L_OUT 223
#define TX 32              // tile rows
#define TY 64              // tile cols
#define HR 33              // halo rows
#define PITCH 66           // half2 words per table row (even -> 8B rows)
#define PI_F 3.14159265358979323846f

struct H2X2 { __half2 a, b; };

__global__ __launch_bounds__(256) void quanv_main_kernel(
    const float* __restrict__ in,   // (64,1,224,224)
    const float* __restrict__ w,    // (1,4)
    float* __restrict__ out)        // (64,4,223,223)
{
    __shared__ __half2 T01[HR][PITCH];
    __shared__ __half2 T23[HR][PITCH];

    const int tid = threadIdx.x;
    const int b  = blockIdx.z;
    const int x0 = blockIdx.y * TX;
    const int y0 = blockIdx.x * TY;

    const float4 wv = __ldg(reinterpret_cast<const float4*>(w));
    const float* inb = in + (size_t)b * (H_IN * W_IN);

    __half* p01 = reinterpret_cast<__half*>(T01);
    __half* p23 = reinterpret_cast<__half*>(T23);

    // ---- Main loader: c = tid&63 (cols 0..63), rows r0+{0,4,...,28} ----
    {
        const int c  = tid & 63;
        const int r0 = tid >> 6;                 // 0..3
        const int gy = (y0 + c < W_IN) ? (y0 + c) : (W_IN - 1);
        #pragma unroll
        for (int t = 0; t < 4; t++) {
            const int ra = r0 + 8 * t;
            const int rc = ra + 4;
            const int gxa = (x0 + ra < H_IN) ? (x0 + ra) : (H_IN - 1);
            const int gxc = (x0 + rc < H_IN) ? (x0 + rc) : (H_IN - 1);
            const float va = __ldg(&inb[gxa * W_IN + gy]);
            const float vc = __ldg(&inb[gxc * W_IN + gy]);
            // element (ra,c)
            p01[ra * 2 * PITCH + 2 * c] = __float2half_rn(__cosf(fmaf(va, PI_F, wv.x)));
            p23[ra * 2 * PITCH + 2 * c] = __float2half_rn(__cosf(fmaf(va, PI_F, wv.z)));
            // element (rc,c)
            p01[rc * 2 * PITCH + 2 * c] = __float2half_rn(__cosf(fmaf(vc, PI_F, wv.x)));
            p23[rc * 2 * PITCH + 2 * c] = __float2half_rn(__cosf(fmaf(vc, PI_F, wv.z)));
            if (c > 0) {
                p01[ra * 2 * PITCH + 2 * c - 1] = __float2half_rn(__cosf(fmaf(va, PI_F, wv.y)));
                p23[ra * 2 * PITCH + 2 * c - 1] = __float2half_rn(__cosf(fmaf(va, PI_F, wv.w)));
                p01[rc * 2 * PITCH + 2 * c - 1] = __float2half_rn(__cosf(fmaf(vc, PI_F, wv.y)));
                p23[rc * 2 * PITCH + 2 * c - 1] = __float2half_rn(__cosf(fmaf(vc, PI_F, wv.w)));
            }
        }
    }
    // ---- Row 32 (cols 0..63) by tid 0..63 ----
    if (tid < 64) {
        const int c = tid;
        const int gx = (x0 + 32 < H_IN) ? (x0 + 32) : (H_IN - 1);
        const int gy = (y0 + c < W_IN) ? (y0 + c) : (W_IN - 1);
        const float v = __ldg(&inb[gx * W_IN + gy]);
        p01[32 * 2 * PITCH + 2 * c] = __float2half_rn(__cosf(fmaf(v, PI_F, wv.x)));
        p23[32 * 2 * PITCH + 2 * c] = __float2half_rn(__cosf(fmaf(v, PI_F, wv.z)));
        if (c > 0) {
            p01[32 * 2 * PITCH + 2 * c - 1] = __float2half_rn(__cosf(fmaf(v, PI_F, wv.y)));
            p23[32 * 2 * PITCH + 2 * c - 1] = __float2half_rn(__cosf(fmaf(v, PI_F, wv.w)));
        }
    }
    // ---- Col 64 (rows 0..32) by tid 64..96: feeds hi halves of word 63 ----
    if (tid >= 64 && tid < 97) {
        const int r = tid - 64;
        const int gx = (x0 + r < H_IN) ? (x0 + r) : (H_IN - 1);
        const int gy = (y0 + 64 < W_IN) ? (y0 + 64) : (W_IN - 1);
        const float v = __ldg(&inb[gx * W_IN + gy]);
        p01[r * 2 * PITCH + 127] = __float2half_rn(__cosf(fmaf(v, PI_F, wv.y)));
        p23[r * 2 * PITCH + 127] = __float2half_rn(__cosf(fmaf(v, PI_F, wv.w)));
    }
    __syncthreads();

    // ---- Consumer: lane -> y-pair (2*lane), wg -> row group; 4 rows x 2 y ----
    const int lane = tid & 31;
    const int wg   = tid >> 5;
    const int c0 = 2 * lane;
    const int y  = y0 + c0;
    if (y >= L_OUT) return;
    const bool pair = (y + 1 < L_OUT);
    const bool evenrow = ((wg & 1) == 0);     // row parity == wg parity

    const size_t plane = (size_t)L_OUT * L_OUT;
    float* o = out + (size_t)b * 4 * plane + (size_t)(x0 + wg) * L_OUT + y;

    #pragma unroll
    for (int k = 0; k < 4; k++) {
        const int rx = wg + 8 * k;
        if (x0 + rx < L_OUT) {
            const H2X2 u01 = *reinterpret_cast<const H2X2*>(&T01[rx    ][c0]);
            const H2X2 u23 = *reinterpret_cast<const H2X2*>(&T23[rx + 1][c0]);
            const float2 zA0 = __half22float2(u01.a);   // (Z0,Z1) px y
            const float2 zA1 = __half22float2(u01.b);   // (Z0,Z1) px y+1
            const float2 zB0 = __half22float2(u23.a);   // (Z2,Z3) px y
            const float2 zB1 = __half22float2(u23.b);   // (Z2,Z3) px y+1

            const float p01a = zA0.x * zA0.y,  p23a = zB0.x * zB0.y;
            const float ch0a = zA0.y * p23a,   ch2a = p01a * zB0.x;
            const float ch3a = p01a * p23a;
            const float p01b = zA1.x * zA1.y,  p23b = zB1.x * zB1.y;
            const float ch0b = zA1.y * p23b,   ch2b = p01b * zB1.x;
            const float ch3b = p01b * p23b;

            if (pair) {
                if (evenrow) {   // ch0, ch2 are 8B-aligned
                    *reinterpret_cast<float2*>(o)             = make_float2(ch0a, ch0b);
                    *reinterpret_cast<float2*>(o + 2 * plane) = make_float2(ch2a, ch2b);
                    o[plane] = p01a;     o[plane + 1] = p01b;
                    o[3 * plane] = ch3a; o[3 * plane + 1] = ch3b;
                } else {         // ch1, ch3 are 8B-aligned
                    *reinterpret_cast<float2*>(o + plane)     = make_float2(p01a, p01b);
                    *reinterpret_cast<float2*>(o + 3 * plane) = make_float2(ch3a, ch3b);
                    o[0] = ch0a;         o[1] = ch0b;
                    o[2 * plane] = ch2a; o[2 * plane + 1] = ch2b;
                }
            } else {
                o[0] = ch0a; o[plane] = p01a; o[2 * plane] = ch2a; o[3 * plane] = ch3a;
            }
        }
        o += 8 * L_OUT;
    }
}

extern "C" void kernel_launch(void* const* d_in, const int* in_sizes, int n_in,
                              void* d_out, int out_size) {
    const float* inputs = (const float*)d_in[0];   // (64,1,224,224) float32
    const float* weight = (const float*)d_in[1];   // (1,4) float32
    float* out = (float*)d_out;                    // (64,4,223,223) float32

    dim3 grid((L_OUT + TY - 1) / TY,   // 4 col tiles
              (L_OUT + TX - 1) / TX,   // 7 row tiles
              64);                      // batch
    quanv_main_kernel<<<grid, 256>>>(inputs, weight, out);
}